// round 9
// baseline (speedup 1.0000x reference)
#include <cuda_runtime.h>

// ---------------------------------------------------------------------------
// RgbNet, R9: tensor-core MLP (mma.sync m16n8k8 tf32, 3xTF32 for fp32 acc).
//  K1 encode: thread per (ray, level), corner cache; writes g_feat4[ray][30]
//             (ray-major float4). Also packs W1/W2/W3 into B-fragment order
//             (hi/lo tf32 interleaved uint4) for conflict-free LDS.128.
//  K2 mlp:    128 blocks x 512 thr x 128 rays (one wave, 1 block/SM).
//             Warp = 2 M-tiles x 2 N-tiles; acts in stride-68/132 smem
//             (stride mod 32 == 4 -> conflict-free A fragments);
//             cp.async double-buffers W2/W3 behind compute.
// ---------------------------------------------------------------------------

namespace {
constexpr int NRAYS   = 16384;
constexpr int NSAMP   = 300;
constexpr unsigned HSIZE = 1u << 19;
constexpr unsigned HMASK = HSIZE - 1u;

constexpr int ENC_THREADS = 256;
constexpr int ENC_BLOCKS  = (NRAYS * 6) / ENC_THREADS;   // 384

constexpr int MLP_THREADS = 512;     // 16 warps
constexpr int MLP_RPB     = 128;     // rays per block
constexpr int MLP_BLOCKS  = NRAYS / MLP_RPB;             // 128

// packed weight sizes (uint4 units): (K/8 ktiles) * 8 ntiles * 32 lanes
constexpr int W1_PK = 15 * 8 * 32;   // 3840
constexpr int W2_PK = 8 * 8 * 32;    // 2048
constexpr int W3_PK = 8 * 8 * 32;    // 2048
constexpr int WPK_TOTAL = W1_PK + W2_PK + W3_PK;         // 7936

// K2 shared layout (float offsets)
constexpr int OFF_F   = 0;                   // F  [128][132] (feats / h2)
constexpr int OFF_H   = OFF_F + 128 * 132;   // H  [128][68]  (h1 / h3)
constexpr int OFF_W0  = OFF_H + 128 * 68;    // Wbuf0: 15360 floats (W1, W3)
constexpr int OFF_W1B = OFF_W0 + 15360;      // Wbuf1: 8192 floats  (W2)
constexpr int OFF_BS  = OFF_W1B + 8192;      // b1,b2,b3 (192) + b4 (4) + W4 (192)
constexpr int SH_FLOATS = OFF_BS + 388;      // 49540 floats = 198160 B
}

__device__ float4 g_feat4[NRAYS * 30];       // [ray][30] = [ray][k/4]
__device__ uint4  g_Wpack[WPK_TOTAL];        // B-fragment packed, hi/lo tf32

// ---- tf32 helpers -----------------------------------------------------------
__device__ __forceinline__ void split_tf32(float v, unsigned& hi, unsigned& lo) {
    asm("cvt.rna.tf32.f32 %0, %1;" : "=r"(hi) : "f"(v));
    const float lof = v - __uint_as_float(hi);
    asm("cvt.rna.tf32.f32 %0, %1;" : "=r"(lo) : "f"(lof));
}

__device__ __forceinline__ void mma_tf32(float* c, const unsigned* a,
                                         const unsigned b0, const unsigned b1) {
    asm volatile(
        "mma.sync.aligned.m16n8k8.row.col.f32.tf32.tf32.f32 "
        "{%0,%1,%2,%3}, {%4,%5,%6,%7}, {%8,%9}, {%0,%1,%2,%3};"
        : "+f"(c[0]), "+f"(c[1]), "+f"(c[2]), "+f"(c[3])
        : "r"(a[0]), "r"(a[1]), "r"(a[2]), "r"(a[3]), "r"(b0), "r"(b1));
}

// ---- cp.async helpers -------------------------------------------------------
__device__ __forceinline__ void cp16(unsigned dst_smem, const void* src) {
    asm volatile("cp.async.ca.shared.global [%0], [%1], 16;"
                 :: "r"(dst_smem), "l"(src));
}
#define CP_COMMIT() asm volatile("cp.async.commit_group;" ::: "memory")
#define CP_WAIT(n)  asm volatile("cp.async.wait_group %0;" :: "n"(n) : "memory")

// ===========================================================================
// Kernel 1: encoding + weight packing
// ===========================================================================
__global__ __launch_bounds__(ENC_THREADS)
void encode_kernel(const float* __restrict__ x,       // [N,4]
                   const int*   __restrict__ ifirst,  // [N]
                   const float* __restrict__ emb,     // [6,2^19,4]
                   const float* __restrict__ W1,      // [64][120]
                   const float* __restrict__ W2,      // [64][64]
                   const float* __restrict__ W3)      // [64][64]
{
    const int t = blockIdx.x * ENC_THREADS + threadIdx.x;

    // ---- piggyback: pack weights into B-fragment order (hi/lo tf32) -------
    if (t < WPK_TOTAL) {
        const float* Ws; int K, u = t;
        if (u < W1_PK)               { Ws = W1; K = 120; }
        else if (u < W1_PK + W2_PK)  { Ws = W2; K = 64; u -= W1_PK; }
        else                         { Ws = W3; K = 64; u -= W1_PK + W2_PK; }
        const int kt = u >> 8, rem = u & 255;
        const int nt = rem >> 5, lane = rem & 31;
        const int g = lane >> 2, tg = lane & 3;
        const int k0 = kt * 8 + tg, n = nt * 8 + g;
        const float v0 = Ws[n * K + k0];
        const float v1 = Ws[n * K + k0 + 4];
        unsigned h0, l0, h1, l1;
        split_tf32(v0, h0, l0);
        split_tf32(v1, h1, l1);
        g_Wpack[t] = make_uint4(h0, h1, l0, l1);
    }

    // ---- encoding task: t = level*16384 + ray ------------------------------
    const int ray = t & (NRAYS - 1);
    const int l   = t >> 14;                 // 0..5, uniform per warp

    const float4 xr  = __ldg(reinterpret_cast<const float4*>(x) + ray);
    const int    if0 = __ldg(ifirst + ray);

    const int   R   = 4 << l;
    const float fR  = (float)R;
    const int   Rp1 = R + 1;
    const float4* __restrict__ tab =
        reinterpret_cast<const float4*>(emb) + (size_t)l * HSIZE;

    int    prev_key = -1;
    float4 cc[8];

    #pragma unroll
    for (int s = 0; s < 5; s++) {
        int sc = if0 + s - 2;
        sc = sc < 0 ? 0 : (sc > NSAMP - 1 ? NSAMP - 1 : sc);
        const float tt  = (float)sc * (1.0f / 299.0f);
        const float omt = 1.0f - tt;
        const float px = xr.x * omt + xr.z * tt;
        const float py = xr.y * omt + xr.w * tt;
        const float pz = tt;

        const float fx = px * fR, fy = py * fR, fz = pz * fR;
        const float flx = floorf(fx), fly = floorf(fy), flz = floorf(fz);
        const int ix = (int)flx, iy = (int)fly, iz = (int)flz;
        const float wx = fx - flx, wy = fy - fly, wz = fz - flz;

        const int key = ix | (iy << 10) | (iz << 20);
        if (key != prev_key) {
            prev_key = key;
            #pragma unroll
            for (int c = 0; c < 8; c++) {
                const int bx = (c >> 2) & 1, by = (c >> 1) & 1, bz = c & 1;
                int cx = ix + bx; cx = cx > R ? R : cx;
                int cy = iy + by; cy = cy > R ? R : cy;
                int cz = iz + bz; cz = cz > R ? R : cz;
                const unsigned id_dense =
                    (unsigned)(cx + cy * Rp1 + cz * Rp1 * Rp1);
                const unsigned id_hash =
                    ((unsigned)cx ^ ((unsigned)cy * 2654435761u)
                                 ^ ((unsigned)cz * 805459861u)) & HMASK;
                const unsigned idx = (l == 5) ? id_hash : id_dense;
                cc[c] = __ldg(tab + idx);
            }
        }

        float ax = 0.f, ay = 0.f, az = 0.f, aw = 0.f;
        #pragma unroll
        for (int c = 0; c < 8; c++) {
            const int bx = (c >> 2) & 1, by = (c >> 1) & 1, bz = c & 1;
            const float wgt = (bx ? wx : 1.0f - wx)
                            * (by ? wy : 1.0f - wy)
                            * (bz ? wz : 1.0f - wz);
            ax = fmaf(wgt, cc[c].x, ax);
            ay = fmaf(wgt, cc[c].y, ay);
            az = fmaf(wgt, cc[c].z, az);
            aw = fmaf(wgt, cc[c].w, aw);
        }

        g_feat4[(size_t)ray * 30 + (s * 6 + l)] = make_float4(ax, ay, az, aw);
    }
}

// ===========================================================================
// Kernel 2: tensor-core MLP
// ===========================================================================

// One layer: warp covers M-tiles {2mp, 2mp+1} x N-tiles {2nq, 2nq+1}.
// actIn: [128][STRIDE] fp32; wb: packed B fragments; actOut: [128][68].
template <int KSTEPS, int STRIDE>
__device__ __forceinline__ void mma_layer(const float* __restrict__ actIn,
                                          const float* __restrict__ wb,
                                          const float* __restrict__ bias,
                                          float*       __restrict__ actOut,
                                          int mp, int nq, int lane) {
    const int g = lane >> 2, tg = lane & 3;
    const int rbase = mp * 32 + g;

    float acc[2][2][4];
    #pragma unroll
    for (int m = 0; m < 2; m++)
        #pragma unroll
        for (int j = 0; j < 2; j++) {
            const int n0 = (nq * 2 + j) * 8 + 2 * tg;
            const float bc0 = bias[n0], bc1 = bias[n0 + 1];
            acc[m][j][0] = bc0; acc[m][j][1] = bc1;
            acc[m][j][2] = bc0; acc[m][j][3] = bc1;
        }

    const float* a00 = actIn + (size_t)rbase * STRIDE;        // rows rbase
    const float* a01 = a00 + 8 * STRIDE;                      // +8
    const float* a10 = a00 + 16 * STRIDE;                     // +16
    const float* a11 = a00 + 24 * STRIDE;                     // +24

    #pragma unroll 4
    for (int kt = 0; kt < KSTEPS; kt++) {
        const int kb = kt * 8;
        unsigned ah[2][4], al[2][4];
        split_tf32(a00[kb + tg],     ah[0][0], al[0][0]);
        split_tf32(a01[kb + tg],     ah[0][1], al[0][1]);
        split_tf32(a00[kb + tg + 4], ah[0][2], al[0][2]);
        split_tf32(a01[kb + tg + 4], ah[0][3], al[0][3]);
        split_tf32(a10[kb + tg],     ah[1][0], al[1][0]);
        split_tf32(a11[kb + tg],     ah[1][1], al[1][1]);
        split_tf32(a10[kb + tg + 4], ah[1][2], al[1][2]);
        split_tf32(a11[kb + tg + 4], ah[1][3], al[1][3]);

        #pragma unroll
        for (int j = 0; j < 2; j++) {
            const uint4 bw = *reinterpret_cast<const uint4*>(
                wb + ((size_t)((kt * 8 + nq * 2 + j) * 32) + lane) * 4);
            #pragma unroll
            for (int m = 0; m < 2; m++) {
                mma_tf32(acc[m][j], ah[m], bw.x, bw.y);   // Ahi * Bhi
                mma_tf32(acc[m][j], ah[m], bw.z, bw.w);   // Ahi * Blo
                mma_tf32(acc[m][j], al[m], bw.x, bw.y);   // Alo * Bhi
            }
        }
    }

    #pragma unroll
    for (int m = 0; m < 2; m++) {
        const int r0 = rbase + 16 * m, r1 = r0 + 8;
        #pragma unroll
        for (int j = 0; j < 2; j++) {
            const int n0 = (nq * 2 + j) * 8 + 2 * tg;
            *reinterpret_cast<float2*>(actOut + r0 * 68 + n0) =
                make_float2(fmaxf(acc[m][j][0], 0.0f),
                            fmaxf(acc[m][j][1], 0.0f));
            *reinterpret_cast<float2*>(actOut + r1 * 68 + n0) =
                make_float2(fmaxf(acc[m][j][2], 0.0f),
                            fmaxf(acc[m][j][3], 0.0f));
        }
    }
}

__global__ __launch_bounds__(MLP_THREADS)
void mlp_kernel(const float* __restrict__ b1, const float* __restrict__ b2,
                const float* __restrict__ b3,
                const float* __restrict__ W4, const float* __restrict__ b4,
                float* __restrict__ out)
{
    extern __shared__ float sh[];
    float* F   = sh + OFF_F;
    float* H   = sh + OFF_H;
    float* W0  = sh + OFF_W0;
    float* W1B = sh + OFF_W1B;
    float* BS  = sh + OFF_BS;

    const int tid  = threadIdx.x;
    const int ray0 = blockIdx.x * MLP_RPB;

    const unsigned sW0  = (unsigned)__cvta_generic_to_shared(W0);
    const unsigned sW1B = (unsigned)__cvta_generic_to_shared(W1B);

    // ---- stage feats: g_feat4 [ray][30] -> F [128][132] --------------------
    for (int i = tid; i < 128 * 30; i += MLP_THREADS) {
        const int r = i / 30, j = i - r * 30;
        const float4 v = g_feat4[(size_t)(ray0 + r) * 30 + j];
        *reinterpret_cast<float4*>(F + r * 132 + j * 4) = v;
    }
    // ---- cp.async W1 (group 0), W2 (group 1) -------------------------------
    for (int i = tid; i < W1_PK; i += MLP_THREADS)
        cp16(sW0 + i * 16, g_Wpack + i);
    CP_COMMIT();
    for (int i = tid; i < W2_PK; i += MLP_THREADS)
        cp16(sW1B + i * 16, g_Wpack + W1_PK + i);
    CP_COMMIT();
    // ---- biases + W4 --------------------------------------------------------
    if (tid < 64) {
        BS[tid]       = __ldg(b1 + tid);
        BS[64 + tid]  = __ldg(b2 + tid);
        BS[128 + tid] = __ldg(b3 + tid);
    }
    if (tid < 4)   BS[192 + tid] = (tid < 3) ? __ldg(b4 + tid) : 0.0f;
    if (tid < 192) BS[196 + tid] = __ldg(W4 + tid);

    CP_WAIT(1);                 // W1 arrived (own thread's)
    __syncthreads();            // feats + W1 + biases visible block-wide

    const int lane = tid & 31;
    const int warp = tid >> 5;              // 0..15
    const int mp   = warp & 3;              // M-pair (rays 32mp..32mp+31)
    const int nq   = warp >> 2;             // N-quad (outs 16nq..16nq+15)

    // ---- layer 1: F (K=120) -> H -------------------------------------------
    mma_layer<15, 132>(F, W0, BS, H, mp, nq, lane);
    __syncthreads();            // h1 visible, W0 free

    // prefetch W3 into W0 (group 2)
    for (int i = tid; i < W3_PK; i += MLP_THREADS)
        cp16(sW0 + i * 16, g_Wpack + W1_PK + W2_PK + i);
    CP_COMMIT();
    CP_WAIT(1);                 // W2 arrived
    __syncthreads();

    // ---- layer 2: H -> F (as stride-68) ------------------------------------
    mma_layer<8, 68>(H, W1B, BS + 64, F, mp, nq, lane);
    __syncthreads();
    CP_WAIT(0);                 // W3 arrived
    __syncthreads();

    // ---- layer 3: F -> H ----------------------------------------------------
    mma_layer<8, 68>(F, W0, BS + 128, H, mp, nq, lane);
    __syncthreads();

    // ---- layer 4: 64 -> 3, one thread per ray -------------------------------
    if (tid < MLP_RPB) {
        const float* W4s = BS + 196;
        const float* hrow = H + tid * 68;
        float a0 = BS[192], a1 = BS[193], a2 = BS[194];
        #pragma unroll 8
        for (int k = 0; k < 64; k++) {
            const float hv = hrow[k];
            a0 = fmaf(hv, W4s[k],       a0);
            a1 = fmaf(hv, W4s[64 + k],  a1);
            a2 = fmaf(hv, W4s[128 + k], a2);
        }
        float* o = out + (size_t)(ray0 + tid) * 3;
        o[0] = a0; o[1] = a1; o[2] = a2;
    }
}

extern "C" void kernel_launch(void* const* d_in, const int* in_sizes, int n_in,
                              void* d_out, int out_size) {
    const float* x    = (const float*)d_in[0];
    const int*   idxf = (const int*)  d_in[1];
    const float* emb  = (const float*)d_in[2];
    const float* W1   = (const float*)d_in[3];
    const float* b1   = (const float*)d_in[4];
    const float* W2   = (const float*)d_in[5];
    const float* b2   = (const float*)d_in[6];
    const float* W3   = (const float*)d_in[7];
    const float* b3   = (const float*)d_in[8];
    const float* W4   = (const float*)d_in[9];
    const float* b4   = (const float*)d_in[10];
    float* out = (float*)d_out;

    encode_kernel<<<ENC_BLOCKS, ENC_THREADS>>>(x, idxf, emb, W1, W2, W3);

    const size_t shbytes = (size_t)SH_FLOATS * sizeof(float);   // 198160 B
    cudaFuncSetAttribute(mlp_kernel,
                         cudaFuncAttributeMaxDynamicSharedMemorySize,
                         (int)shbytes);
    mlp_kernel<<<MLP_BLOCKS, MLP_THREADS, shbytes>>>(b1, b2, b3, W4, b4, out);
}

// round 10
// speedup vs baseline: 1.1831x; 1.1831x over previous
#include <cuda_runtime.h>

// ---------------------------------------------------------------------------
// RgbNet, R10: tensor-core MLP, 2-term TF32 (A pre-rounded, B split hi/lo).
//  K1 encode: thread per (ray, level), corner cache; writes g_feat[k][ray]
//             (k-major, coalesced) with values pre-rounded to tf32.
//             Packs W1/W2/W3 into B-fragment hi/lo uint4 order.
//  K2 mlp:    128 blocks x 512 thr x 128 rays; stages feats with transpose
//             into [128][132] smem; warp = 2 M-tiles x 2 N-tiles;
//             per k-tile: 8 LDS.32 (A) + 2 LDS.128 (B) + 8 MMA.
//             cp.async double-buffers W2/W3 behind compute.
// ---------------------------------------------------------------------------

namespace {
constexpr int NRAYS   = 16384;
constexpr int NSAMP   = 300;
constexpr unsigned HSIZE = 1u << 19;
constexpr unsigned HMASK = HSIZE - 1u;

constexpr int ENC_THREADS = 256;
constexpr int ENC_BLOCKS  = (NRAYS * 6) / ENC_THREADS;   // 384

constexpr int MLP_THREADS = 512;     // 16 warps
constexpr int MLP_RPB     = 128;     // rays per block
constexpr int MLP_BLOCKS  = NRAYS / MLP_RPB;             // 128

// packed weight sizes (uint4 units): (K/8 ktiles) * 8 ntiles * 32 lanes
constexpr int W1_PK = 15 * 8 * 32;   // 3840
constexpr int W2_PK = 8 * 8 * 32;    // 2048
constexpr int W3_PK = 8 * 8 * 32;    // 2048
constexpr int WPK_TOTAL = W1_PK + W2_PK + W3_PK;         // 7936

// K2 shared layout (float offsets)
constexpr int OFF_F   = 0;                   // F  [128][132] (feats / h2)
constexpr int OFF_H   = OFF_F + 128 * 132;   // H  [128][68]  (h1 / h3)
constexpr int OFF_W0  = OFF_H + 128 * 68;    // Wbuf0: 15360 floats (W1, W3)
constexpr int OFF_W1B = OFF_W0 + 15360;      // Wbuf1: 8192 floats  (W2)
constexpr int OFF_BS  = OFF_W1B + 8192;      // b1,b2,b3,b4,W4
constexpr int SH_FLOATS = OFF_BS + 388;      // 49540 floats = 198160 B
}

__device__ float g_feat[120 * NRAYS];        // [k][ray], tf32-rounded values
__device__ uint4 g_Wpack[WPK_TOTAL];         // B fragments: (hi0,hi1,lo0,lo1)

// ---- tf32 helpers -----------------------------------------------------------
__device__ __forceinline__ float tf32r(float v) {
    unsigned u;
    asm("cvt.rna.tf32.f32 %0, %1;" : "=r"(u) : "f"(v));
    return __uint_as_float(u);
}
__device__ __forceinline__ void split_tf32(float v, unsigned& hi, unsigned& lo) {
    asm("cvt.rna.tf32.f32 %0, %1;" : "=r"(hi) : "f"(v));
    const float lof = v - __uint_as_float(hi);
    asm("cvt.rna.tf32.f32 %0, %1;" : "=r"(lo) : "f"(lof));
}
__device__ __forceinline__ void mma_tf32(float* c, const unsigned* a,
                                         const unsigned b0, const unsigned b1) {
    asm volatile(
        "mma.sync.aligned.m16n8k8.row.col.f32.tf32.tf32.f32 "
        "{%0,%1,%2,%3}, {%4,%5,%6,%7}, {%8,%9}, {%0,%1,%2,%3};"
        : "+f"(c[0]), "+f"(c[1]), "+f"(c[2]), "+f"(c[3])
        : "r"(a[0]), "r"(a[1]), "r"(a[2]), "r"(a[3]), "r"(b0), "r"(b1));
}

// ---- cp.async helpers -------------------------------------------------------
__device__ __forceinline__ void cp16(unsigned dst_smem, const void* src) {
    asm volatile("cp.async.ca.shared.global [%0], [%1], 16;"
                 :: "r"(dst_smem), "l"(src));
}
#define CP_COMMIT() asm volatile("cp.async.commit_group;" ::: "memory")
#define CP_WAIT(n)  asm volatile("cp.async.wait_group %0;" :: "n"(n) : "memory")

// ===========================================================================
// Kernel 1: encoding + weight packing
// ===========================================================================
__global__ __launch_bounds__(ENC_THREADS)
void encode_kernel(const float* __restrict__ x,       // [N,4]
                   const int*   __restrict__ ifirst,  // [N]
                   const float* __restrict__ emb,     // [6,2^19,4]
                   const float* __restrict__ W1,      // [64][120]
                   const float* __restrict__ W2,      // [64][64]
                   const float* __restrict__ W3)      // [64][64]
{
    const int t = blockIdx.x * ENC_THREADS + threadIdx.x;

    // ---- piggyback: pack weights into B-fragment order (hi/lo tf32) -------
    if (t < WPK_TOTAL) {
        const float* Ws; int K, u = t;
        if (u < W1_PK)               { Ws = W1; K = 120; }
        else if (u < W1_PK + W2_PK)  { Ws = W2; K = 64; u -= W1_PK; }
        else                         { Ws = W3; K = 64; u -= W1_PK + W2_PK; }
        const int kt = u >> 8, rem = u & 255;
        const int nt = rem >> 5, lane = rem & 31;
        const int g = lane >> 2, tg = lane & 3;
        const int k0 = kt * 8 + tg, n = nt * 8 + g;
        const float v0 = Ws[n * K + k0];
        const float v1 = Ws[n * K + k0 + 4];
        unsigned h0, l0, h1, l1;
        split_tf32(v0, h0, l0);
        split_tf32(v1, h1, l1);
        g_Wpack[t] = make_uint4(h0, h1, l0, l1);
    }

    // ---- encoding task: t = level*16384 + ray ------------------------------
    const int ray = t & (NRAYS - 1);
    const int l   = t >> 14;                 // 0..5, uniform per warp

    const float4 xr  = __ldg(reinterpret_cast<const float4*>(x) + ray);
    const int    if0 = __ldg(ifirst + ray);

    const int   R   = 4 << l;
    const float fR  = (float)R;
    const int   Rp1 = R + 1;
    const float4* __restrict__ tab =
        reinterpret_cast<const float4*>(emb) + (size_t)l * HSIZE;

    int    prev_key = -1;
    float4 cc[8];

    #pragma unroll
    for (int s = 0; s < 5; s++) {
        int sc = if0 + s - 2;
        sc = sc < 0 ? 0 : (sc > NSAMP - 1 ? NSAMP - 1 : sc);
        const float tt  = (float)sc * (1.0f / 299.0f);
        const float omt = 1.0f - tt;
        const float px = xr.x * omt + xr.z * tt;
        const float py = xr.y * omt + xr.w * tt;
        const float pz = tt;

        const float fx = px * fR, fy = py * fR, fz = pz * fR;
        const float flx = floorf(fx), fly = floorf(fy), flz = floorf(fz);
        const int ix = (int)flx, iy = (int)fly, iz = (int)flz;
        const float wx = fx - flx, wy = fy - fly, wz = fz - flz;

        const int key = ix | (iy << 10) | (iz << 20);
        if (key != prev_key) {
            prev_key = key;
            #pragma unroll
            for (int c = 0; c < 8; c++) {
                const int bx = (c >> 2) & 1, by = (c >> 1) & 1, bz = c & 1;
                int cx = ix + bx; cx = cx > R ? R : cx;
                int cy = iy + by; cy = cy > R ? R : cy;
                int cz = iz + bz; cz = cz > R ? R : cz;
                const unsigned id_dense =
                    (unsigned)(cx + cy * Rp1 + cz * Rp1 * Rp1);
                const unsigned id_hash =
                    ((unsigned)cx ^ ((unsigned)cy * 2654435761u)
                                 ^ ((unsigned)cz * 805459861u)) & HMASK;
                const unsigned idx = (l == 5) ? id_hash : id_dense;
                cc[c] = __ldg(tab + idx);
            }
        }

        float ax = 0.f, ay = 0.f, az = 0.f, aw = 0.f;
        #pragma unroll
        for (int c = 0; c < 8; c++) {
            const int bx = (c >> 2) & 1, by = (c >> 1) & 1, bz = c & 1;
            const float wgt = (bx ? wx : 1.0f - wx)
                            * (by ? wy : 1.0f - wy)
                            * (bz ? wz : 1.0f - wz);
            ax = fmaf(wgt, cc[c].x, ax);
            ay = fmaf(wgt, cc[c].y, ay);
            az = fmaf(wgt, cc[c].z, az);
            aw = fmaf(wgt, cc[c].w, aw);
        }

        const int kb = (s * 6 + l) * 4;
        g_feat[(size_t)(kb + 0) * NRAYS + ray] = tf32r(ax);
        g_feat[(size_t)(kb + 1) * NRAYS + ray] = tf32r(ay);
        g_feat[(size_t)(kb + 2) * NRAYS + ray] = tf32r(az);
        g_feat[(size_t)(kb + 3) * NRAYS + ray] = tf32r(aw);
    }
}

// ===========================================================================
// Kernel 2: tensor-core MLP (2-term tf32)
// ===========================================================================

// One layer: warp covers M-tiles {2mp, 2mp+1} x N-tiles pair nq.
// actIn values are already tf32-rounded floats.
template <int KSTEPS, int STRIDE>
__device__ __forceinline__ void mma_layer(const float* __restrict__ actIn,
                                          const float* __restrict__ wb,
                                          const float* __restrict__ bias,
                                          float*       __restrict__ actOut,
                                          int mp, int nq, int lane) {
    const int g = lane >> 2, tg = lane & 3;
    const int rbase = mp * 32 + g;

    float acc[2][2][4];
    #pragma unroll
    for (int m = 0; m < 2; m++)
        #pragma unroll
        for (int j = 0; j < 2; j++) {
            const int n0 = (nq * 2 + j) * 8 + 2 * tg;
            const float bc0 = bias[n0], bc1 = bias[n0 + 1];
            acc[m][j][0] = bc0; acc[m][j][1] = bc1;
            acc[m][j][2] = bc0; acc[m][j][3] = bc1;
        }

    const unsigned* a00 = reinterpret_cast<const unsigned*>(
        actIn + (size_t)rbase * STRIDE);
    const unsigned* a01 = a00 + 8 * STRIDE;
    const unsigned* a10 = a00 + 16 * STRIDE;
    const unsigned* a11 = a00 + 24 * STRIDE;

    #pragma unroll
    for (int kt = 0; kt < KSTEPS; kt++) {
        const int kb = kt * 8;
        unsigned ah[2][4];
        ah[0][0] = a00[kb + tg];     ah[0][1] = a01[kb + tg];
        ah[0][2] = a00[kb + tg + 4]; ah[0][3] = a01[kb + tg + 4];
        ah[1][0] = a10[kb + tg];     ah[1][1] = a11[kb + tg];
        ah[1][2] = a10[kb + tg + 4]; ah[1][3] = a11[kb + tg + 4];

        #pragma unroll
        for (int j = 0; j < 2; j++) {
            const uint4 bw = *reinterpret_cast<const uint4*>(
                wb + ((size_t)((kt * 8 + nq * 2 + j) * 32) + lane) * 4);
            #pragma unroll
            for (int m = 0; m < 2; m++) {
                mma_tf32(acc[m][j], ah[m], bw.x, bw.y);   // Ahi * Bhi
                mma_tf32(acc[m][j], ah[m], bw.z, bw.w);   // Ahi * Blo
            }
        }
    }

    #pragma unroll
    for (int m = 0; m < 2; m++) {
        const int r0 = rbase + 16 * m, r1 = r0 + 8;
        #pragma unroll
        for (int j = 0; j < 2; j++) {
            const int n0 = (nq * 2 + j) * 8 + 2 * tg;
            *reinterpret_cast<float2*>(actOut + r0 * 68 + n0) =
                make_float2(tf32r(fmaxf(acc[m][j][0], 0.0f)),
                            tf32r(fmaxf(acc[m][j][1], 0.0f)));
            *reinterpret_cast<float2*>(actOut + r1 * 68 + n0) =
                make_float2(tf32r(fmaxf(acc[m][j][2], 0.0f)),
                            tf32r(fmaxf(acc[m][j][3], 0.0f)));
        }
    }
}

__global__ __launch_bounds__(MLP_THREADS)
void mlp_kernel(const float* __restrict__ b1, const float* __restrict__ b2,
                const float* __restrict__ b3,
                const float* __restrict__ W4, const float* __restrict__ b4,
                float* __restrict__ out)
{
    extern __shared__ float sh[];
    float* F   = sh + OFF_F;
    float* H   = sh + OFF_H;
    float* W0  = sh + OFF_W0;
    float* W1B = sh + OFF_W1B;
    float* BS  = sh + OFF_BS;

    const int tid  = threadIdx.x;
    const int ray0 = blockIdx.x * MLP_RPB;

    const unsigned sW0  = (unsigned)__cvta_generic_to_shared(W0);
    const unsigned sW1B = (unsigned)__cvta_generic_to_shared(W1B);

    // ---- cp.async W1 (group 0), W2 (group 1) -------------------------------
    for (int i = tid; i < W1_PK; i += MLP_THREADS)
        cp16(sW0 + i * 16, g_Wpack + i);
    CP_COMMIT();
    for (int i = tid; i < W2_PK; i += MLP_THREADS)
        cp16(sW1B + i * 16, g_Wpack + W1_PK + i);
    CP_COMMIT();

    // ---- stage feats: g_feat [k][ray] -> F [128][132] (transpose) ----------
    for (int i = tid; i < 120 * 128; i += MLP_THREADS) {
        const int k = i >> 7, r = i & 127;
        F[r * 132 + k] = __ldg(&g_feat[(size_t)k * NRAYS + ray0 + r]);
    }
    // ---- biases + W4 --------------------------------------------------------
    if (tid < 64) {
        BS[tid]       = __ldg(b1 + tid);
        BS[64 + tid]  = __ldg(b2 + tid);
        BS[128 + tid] = __ldg(b3 + tid);
    }
    if (tid < 4)   BS[192 + tid] = (tid < 3) ? __ldg(b4 + tid) : 0.0f;
    if (tid < 192) BS[196 + tid] = __ldg(W4 + tid);

    CP_WAIT(1);                 // W1 arrived
    __syncthreads();

    const int lane = tid & 31;
    const int warp = tid >> 5;              // 0..15
    const int mp   = warp & 3;              // M-pair (rays 32mp..32mp+31)
    const int nq   = warp >> 2;             // N-quad (outs 16nq..16nq+15)

    // ---- layer 1: F (K=120) -> H -------------------------------------------
    mma_layer<15, 132>(F, W0, BS, H, mp, nq, lane);
    __syncthreads();

    // prefetch W3 into W0 (group 2)
    for (int i = tid; i < W3_PK; i += MLP_THREADS)
        cp16(sW0 + i * 16, g_Wpack + W1_PK + W2_PK + i);
    CP_COMMIT();
    CP_WAIT(1);                 // W2 arrived
    __syncthreads();

    // ---- layer 2: H -> F (as stride-68) ------------------------------------
    mma_layer<8, 68>(H, W1B, BS + 64, F, mp, nq, lane);
    __syncthreads();
    CP_WAIT(0);                 // W3 arrived
    __syncthreads();

    // ---- layer 3: F -> H ----------------------------------------------------
    mma_layer<8, 68>(F, W0, BS + 128, H, mp, nq, lane);
    __syncthreads();

    // ---- layer 4: 64 -> 3, one thread per ray -------------------------------
    if (tid < MLP_RPB) {
        const float* W4s = BS + 196;
        const float* hrow = H + tid * 68;
        float a0 = BS[192], a1 = BS[193], a2 = BS[194];
        #pragma unroll 8
        for (int k = 0; k < 64; k++) {
            const float hv = hrow[k];
            a0 = fmaf(hv, W4s[k],       a0);
            a1 = fmaf(hv, W4s[64 + k],  a1);
            a2 = fmaf(hv, W4s[128 + k], a2);
        }
        float* o = out + (size_t)(ray0 + tid) * 3;
        o[0] = a0; o[1] = a1; o[2] = a2;
    }
}

extern "C" void kernel_launch(void* const* d_in, const int* in_sizes, int n_in,
                              void* d_out, int out_size) {
    const float* x    = (const float*)d_in[0];
    const int*   idxf = (const int*)  d_in[1];
    const float* emb  = (const float*)d_in[2];
    const float* W1   = (const float*)d_in[3];
    const float* b1   = (const float*)d_in[4];
    const float* W2   = (const float*)d_in[5];
    const float* b2   = (const float*)d_in[6];
    const float* W3   = (const float*)d_in[7];
    const float* b3   = (const float*)d_in[8];
    const float* W4   = (const float*)d_in[9];
    const float* b4   = (const float*)d_in[10];
    float* out = (float*)d_out;

    encode_kernel<<<ENC_BLOCKS, ENC_THREADS>>>(x, idxf, emb, W1, W2, W3);

    const size_t shbytes = (size_t)SH_FLOATS * sizeof(float);   // 198160 B
    cudaFuncSetAttribute(mlp_kernel,
                         cudaFuncAttributeMaxDynamicSharedMemorySize,
                         (int)shbytes);
    mlp_kernel<<<MLP_BLOCKS, MLP_THREADS, shbytes>>>(b1, b2, b3, W4, b4, out);
}

// round 11
// speedup vs baseline: 1.2514x; 1.0577x over previous
#include <cuda_runtime.h>

// ---------------------------------------------------------------------------
// RgbNet, R11: single fused kernel (tensor-core MLP, 2-term TF32).
//  Phase 0: pack W1/W2 from global into B-fragment hi/lo smem layout
//           (1 pass: LDG -> tf32 split -> STS.128, conflict-free). Biases.
//  Phase E: encode 128 rays x 6 levels (corner cache) -> F[128][132] smem.
//  Layers:  mma.sync m16n8k8 tf32, D = Ahi*Bhi + Ahi*Blo (A pre-rounded);
//           W3 packed into W1's buffer overlapping layer 2.
//  Layer 4: all 512 threads (ray x k-quarter, shuffle reduce).
//  Grid: 128 blocks x 512 thr x 128 rays, 198KB smem, one wave.
// ---------------------------------------------------------------------------

namespace {
constexpr int NRAYS   = 16384;
constexpr int NSAMP   = 300;
constexpr unsigned HSIZE = 1u << 19;
constexpr unsigned HMASK = HSIZE - 1u;

constexpr int THREADS = 512;     // 16 warps
constexpr int RPB     = 128;     // rays per block
constexpr int BLOCKS  = NRAYS / RPB;     // 128

// packed weight sizes (uint4 units): (K/8) * 8 ntiles * 32 lanes
constexpr int W1_PK = 15 * 8 * 32;   // 3840
constexpr int W2_PK = 8 * 8 * 32;    // 2048
constexpr int W3_PK = 8 * 8 * 32;    // 2048

// shared layout (float offsets)
constexpr int OFF_F   = 0;                   // F  [128][132] (feats / h2)
constexpr int OFF_H   = OFF_F + 128 * 132;   // H  [128][68]  (h1 / h3)
constexpr int OFF_W0  = OFF_H + 128 * 68;    // Wbuf0: 15360 fl (W1, then W3)
constexpr int OFF_W1B = OFF_W0 + 15360;      // Wbuf1: 8192 fl (W2)
constexpr int OFF_BS  = OFF_W1B + 8192;      // b1,b2,b3 (192) b4 (4) W4 (192)
constexpr int SH_FLOATS = OFF_BS + 388;      // 49540 fl = 198160 B
}

// ---- tf32 helpers -----------------------------------------------------------
__device__ __forceinline__ float tf32r(float v) {
    unsigned u;
    asm("cvt.rna.tf32.f32 %0, %1;" : "=r"(u) : "f"(v));
    return __uint_as_float(u);
}
__device__ __forceinline__ void split_tf32(float v, unsigned& hi, unsigned& lo) {
    asm("cvt.rna.tf32.f32 %0, %1;" : "=r"(hi) : "f"(v));
    const float lof = v - __uint_as_float(hi);
    asm("cvt.rna.tf32.f32 %0, %1;" : "=r"(lo) : "f"(lof));
}
__device__ __forceinline__ void mma_tf32(float* c, const unsigned* a,
                                         const unsigned b0, const unsigned b1) {
    asm volatile(
        "mma.sync.aligned.m16n8k8.row.col.f32.tf32.tf32.f32 "
        "{%0,%1,%2,%3}, {%4,%5,%6,%7}, {%8,%9}, {%0,%1,%2,%3};"
        : "+f"(c[0]), "+f"(c[1]), "+f"(c[2]), "+f"(c[3])
        : "r"(a[0]), "r"(a[1]), "r"(a[2]), "r"(a[3]), "r"(b0), "r"(b1));
}

// pack one uint4 slot of weight matrix Ws[N][K] into B-fragment hi/lo order
template <int K>
__device__ __forceinline__ void pack_slot(const float* __restrict__ Ws,
                                          uint4* __restrict__ dst, int u) {
    const int kt = u >> 8, rem = u & 255;
    const int nt = rem >> 5, lane = rem & 31;
    const int g = lane >> 2, tg = lane & 3;
    const int k0 = kt * 8 + tg, n = nt * 8 + g;
    const float v0 = __ldg(Ws + n * K + k0);
    const float v1 = __ldg(Ws + n * K + k0 + 4);
    unsigned h0, l0, h1, l1;
    split_tf32(v0, h0, l0);
    split_tf32(v1, h1, l1);
    dst[u] = make_uint4(h0, h1, l0, l1);
}

// One layer: warp covers M-tiles {2mp,2mp+1} x N-tile pair nq.
// actIn values already tf32-rounded. actOut stride 68.
template <int KSTEPS, int STRIDE>
__device__ __forceinline__ void mma_layer(const float* __restrict__ actIn,
                                          const float* __restrict__ wb,
                                          const float* __restrict__ bias,
                                          float*       __restrict__ actOut,
                                          int mp, int nq, int lane) {
    const int g = lane >> 2, tg = lane & 3;
    const int rbase = mp * 32 + g;

    float acc[2][2][4];
    #pragma unroll
    for (int m = 0; m < 2; m++)
        #pragma unroll
        for (int j = 0; j < 2; j++) {
            const int n0 = (nq * 2 + j) * 8 + 2 * tg;
            const float bc0 = bias[n0], bc1 = bias[n0 + 1];
            acc[m][j][0] = bc0; acc[m][j][1] = bc1;
            acc[m][j][2] = bc0; acc[m][j][3] = bc1;
        }

    const unsigned* a00 = reinterpret_cast<const unsigned*>(
        actIn + (size_t)rbase * STRIDE);
    const unsigned* a01 = a00 + 8 * STRIDE;
    const unsigned* a10 = a00 + 16 * STRIDE;
    const unsigned* a11 = a00 + 24 * STRIDE;

    #pragma unroll
    for (int kt = 0; kt < KSTEPS; kt++) {
        const int kb = kt * 8;
        unsigned ah[2][4];
        ah[0][0] = a00[kb + tg];     ah[0][1] = a01[kb + tg];
        ah[0][2] = a00[kb + tg + 4]; ah[0][3] = a01[kb + tg + 4];
        ah[1][0] = a10[kb + tg];     ah[1][1] = a11[kb + tg];
        ah[1][2] = a10[kb + tg + 4]; ah[1][3] = a11[kb + tg + 4];

        #pragma unroll
        for (int j = 0; j < 2; j++) {
            const uint4 bw = *reinterpret_cast<const uint4*>(
                wb + ((size_t)((kt * 8 + nq * 2 + j) * 32) + lane) * 4);
            #pragma unroll
            for (int m = 0; m < 2; m++) {
                mma_tf32(acc[m][j], ah[m], bw.x, bw.y);   // Ahi * Bhi
                mma_tf32(acc[m][j], ah[m], bw.z, bw.w);   // Ahi * Blo
            }
        }
    }

    #pragma unroll
    for (int m = 0; m < 2; m++) {
        const int r0 = rbase + 16 * m, r1 = r0 + 8;
        #pragma unroll
        for (int j = 0; j < 2; j++) {
            const int n0 = (nq * 2 + j) * 8 + 2 * tg;
            *reinterpret_cast<float2*>(actOut + r0 * 68 + n0) =
                make_float2(tf32r(fmaxf(acc[m][j][0], 0.0f)),
                            tf32r(fmaxf(acc[m][j][1], 0.0f)));
            *reinterpret_cast<float2*>(actOut + r1 * 68 + n0) =
                make_float2(tf32r(fmaxf(acc[m][j][2], 0.0f)),
                            tf32r(fmaxf(acc[m][j][3], 0.0f)));
        }
    }
}

__global__ __launch_bounds__(THREADS)
void rgbnet_fused(const float* __restrict__ x,        // [N,4]
                  const int*   __restrict__ ifirst,   // [N]
                  const float* __restrict__ emb,      // [6,2^19,4]
                  const float* __restrict__ W1, const float* __restrict__ b1,
                  const float* __restrict__ W2, const float* __restrict__ b2,
                  const float* __restrict__ W3, const float* __restrict__ b3,
                  const float* __restrict__ W4, const float* __restrict__ b4,
                  float* __restrict__ out)             // [N,3]
{
    extern __shared__ float sh[];
    float* F   = sh + OFF_F;
    float* H   = sh + OFF_H;
    float* W0  = sh + OFF_W0;
    float* W1B = sh + OFF_W1B;
    float* BS  = sh + OFF_BS;

    const int tid  = threadIdx.x;
    const int ray0 = blockIdx.x * RPB;

    // ---- Phase 0: pack W1 -> W0, W2 -> W1B; biases + W4 --------------------
    for (int u = tid; u < W1_PK; u += THREADS)
        pack_slot<120>(W1, reinterpret_cast<uint4*>(W0), u);
    for (int u = tid; u < W2_PK; u += THREADS)
        pack_slot<64>(W2, reinterpret_cast<uint4*>(W1B), u);
    if (tid < 64) {
        BS[tid]       = __ldg(b1 + tid);
        BS[64 + tid]  = __ldg(b2 + tid);
        BS[128 + tid] = __ldg(b3 + tid);
    }
    if (tid < 4)   BS[192 + tid] = (tid < 3) ? __ldg(b4 + tid) : 0.0f;
    if (tid < 192) BS[196 + tid] = __ldg(W4 + tid);

    // ---- Phase E: encode -> F[128][132] ------------------------------------
    for (int t = tid; t < 6 * RPB; t += THREADS) {
        const int l   = t >> 7;              // level, warp-uniform
        const int col = t & 127;
        const int ray = ray0 + col;

        const float4 xr  = __ldg(reinterpret_cast<const float4*>(x) + ray);
        const int    if0 = __ldg(ifirst + ray);

        const int   R   = 4 << l;
        const float fR  = (float)R;
        const int   Rp1 = R + 1;
        const float4* __restrict__ tab =
            reinterpret_cast<const float4*>(emb) + (size_t)l * HSIZE;

        int    prev_key = -1;
        float4 cc[8];

        #pragma unroll
        for (int s = 0; s < 5; s++) {
            int sc = if0 + s - 2;
            sc = sc < 0 ? 0 : (sc > NSAMP - 1 ? NSAMP - 1 : sc);
            const float tt  = (float)sc * (1.0f / 299.0f);
            const float omt = 1.0f - tt;
            const float px = xr.x * omt + xr.z * tt;
            const float py = xr.y * omt + xr.w * tt;
            const float pz = tt;

            const float fx = px * fR, fy = py * fR, fz = pz * fR;
            const float flx = floorf(fx), fly = floorf(fy), flz = floorf(fz);
            const int ix = (int)flx, iy = (int)fly, iz = (int)flz;
            const float wx = fx - flx, wy = fy - fly, wz = fz - flz;

            const int key = ix | (iy << 10) | (iz << 20);
            if (key != prev_key) {
                prev_key = key;
                #pragma unroll
                for (int c = 0; c < 8; c++) {
                    const int bx = (c >> 2) & 1, by = (c >> 1) & 1, bz = c & 1;
                    int cx = ix + bx; cx = cx > R ? R : cx;
                    int cy = iy + by; cy = cy > R ? R : cy;
                    int cz = iz + bz; cz = cz > R ? R : cz;
                    const unsigned id_dense =
                        (unsigned)(cx + cy * Rp1 + cz * Rp1 * Rp1);
                    const unsigned id_hash =
                        ((unsigned)cx ^ ((unsigned)cy * 2654435761u)
                                     ^ ((unsigned)cz * 805459861u)) & HMASK;
                    const unsigned idx = (l == 5) ? id_hash : id_dense;
                    cc[c] = __ldg(tab + idx);
                }
            }

            float ax = 0.f, ay = 0.f, az = 0.f, aw = 0.f;
            #pragma unroll
            for (int c = 0; c < 8; c++) {
                const int bx = (c >> 2) & 1, by = (c >> 1) & 1, bz = c & 1;
                const float wgt = (bx ? wx : 1.0f - wx)
                                * (by ? wy : 1.0f - wy)
                                * (bz ? wz : 1.0f - wz);
                ax = fmaf(wgt, cc[c].x, ax);
                ay = fmaf(wgt, cc[c].y, ay);
                az = fmaf(wgt, cc[c].z, az);
                aw = fmaf(wgt, cc[c].w, aw);
            }

            const int kb = (s * 6 + l) * 4;
            *reinterpret_cast<float4*>(F + col * 132 + kb) =
                make_float4(tf32r(ax), tf32r(ay), tf32r(az), tf32r(aw));
        }
    }
    __syncthreads();     // F feats + W1/W2 + biases visible

    const int lane = tid & 31;
    const int warp = tid >> 5;              // 0..15
    const int mp   = warp & 3;              // M-pair (rays 32mp..32mp+31)
    const int nq   = warp >> 2;             // N-quad (outs 16nq..16nq+15)

    // ---- layer 1: F (K=120) -> H --------------------------------------------
    mma_layer<15, 132>(F, W0, BS, H, mp, nq, lane);
    __syncthreads();     // H visible; W0 (W1) dead

    // pack W3 into W0 (overlaps layer 2 in the instruction stream)
    for (int u = tid; u < W3_PK; u += THREADS)
        pack_slot<64>(W3, reinterpret_cast<uint4*>(W0), u);

    // ---- layer 2: H -> F ------------------------------------------------------
    mma_layer<8, 68>(H, W1B, BS + 64, F, mp, nq, lane);
    __syncthreads();     // h2 visible AND W3 visible

    // ---- layer 3: F -> H ------------------------------------------------------
    mma_layer<8, 68>(F, W0, BS + 128, H, mp, nq, lane);
    __syncthreads();

    // ---- layer 4: 64 -> 3, all 512 threads (ray x k-quarter) ------------------
    {
        const int ray = tid >> 2;            // 0..127
        const int kq  = tid & 3;             // k-quarter
        const float* hrow = H + ray * 68 + kq * 16;
        const float* W4s  = BS + 196 + kq * 16;
        float a0 = 0.f, a1 = 0.f, a2 = 0.f;
        #pragma unroll
        for (int k = 0; k < 16; k++) {
            const float hv = hrow[k];
            a0 = fmaf(hv, W4s[k],       a0);
            a1 = fmaf(hv, W4s[64 + k],  a1);
            a2 = fmaf(hv, W4s[128 + k], a2);
        }
        a0 += __shfl_xor_sync(0xffffffffu, a0, 1);
        a1 += __shfl_xor_sync(0xffffffffu, a1, 1);
        a2 += __shfl_xor_sync(0xffffffffu, a2, 1);
        a0 += __shfl_xor_sync(0xffffffffu, a0, 2);
        a1 += __shfl_xor_sync(0xffffffffu, a1, 2);
        a2 += __shfl_xor_sync(0xffffffffu, a2, 2);
        if (kq == 0) {
            float* o = out + (size_t)(ray0 + ray) * 3;
            o[0] = a0 + BS[192];
            o[1] = a1 + BS[193];
            o[2] = a2 + BS[194];
        }
    }
}

extern "C" void kernel_launch(void* const* d_in, const int* in_sizes, int n_in,
                              void* d_out, int out_size) {
    const float* x    = (const float*)d_in[0];
    const int*   idxf = (const int*)  d_in[1];
    const float* emb  = (const float*)d_in[2];
    const float* W1   = (const float*)d_in[3];
    const float* b1   = (const float*)d_in[4];
    const float* W2   = (const float*)d_in[5];
    const float* b2   = (const float*)d_in[6];
    const float* W3   = (const float*)d_in[7];
    const float* b3   = (const float*)d_in[8];
    const float* W4   = (const float*)d_in[9];
    const float* b4   = (const float*)d_in[10];
    float* out = (float*)d_out;

    const size_t shbytes = (size_t)SH_FLOATS * sizeof(float);   // 198160 B
    cudaFuncSetAttribute(rgbnet_fused,
                         cudaFuncAttributeMaxDynamicSharedMemorySize,
                         (int)shbytes);
    rgbnet_fused<<<BLOCKS, THREADS, shbytes>>>(
        x, idxf, emb, W1, b1, W2, b2, W3, b3, W4, b4, out);
}